// round 4
// baseline (speedup 1.0000x reference)
#include <cuda_runtime.h>
#include <cuda_fp16.h>

// AdditiveAttention: B=4, Q=512, K=512, H=256, E=256, DV=256
//   q = queries @ W_q^T            [B,Q,H]
//   k = keys    @ W_k^T            [B,K,H]
//   s[b,q,k] = sum_h w_v[h] * tanh(q[b,q,h] + k[b,k,h])
//   attn = softmax_k(s);  out = attn @ values   [B,Q,Dv]

#define BB 4
#define QQ 512
#define KK 512
#define HH 256
#define EE 256
#define DVV 256

// scratch (device globals: no allocations allowed)
__device__ float4 g_qv[BB * QQ * HH / 4];   // 2 MB
__device__ float4 g_kv[BB * KK * HH / 4];   // 2 MB
__device__ float4 g_sv[BB * QQ * KK / 4];   // 4 MB

__device__ __forceinline__ __half2 tanh2(__half2 x) {
    unsigned xi = *(unsigned*)&x, yi;
    asm("tanh.approx.f16x2 %0, %1;" : "=r"(yi) : "r"(xi));
    return *(__half2*)&yi;
}

// FMA-pipe tanh: Pade(5,4) tanh x = x(945+105u+u^2)/(945+420u+15u^2), u=x^2,
// clamped to |x|<=3.5 (abs err <= ~1e-3). Reciprocal of normalized denominator
// D = 1 + u·4/9 + u^2/63 in [1, 8.83] via cubic seed (err <= ~22%) + 3
// self-correcting Newton steps -> f16 floor. ~18 HFMA2-class ops per 2 elems,
// all on the FMA pipe — runs concurrently with MUFU.TANH on the other half.
__device__ __forceinline__ __half2 tanh_pade2(__half2 x) {
    const __half2 one = __floats2half2_rn(1.0f, 1.0f);
    const __half2 two = __floats2half2_rn(2.0f, 2.0f);
    const __half2 cl  = __floats2half2_rn(3.5f, 3.5f);
    const __half2 ncl = __floats2half2_rn(-3.5f, -3.5f);
    const __half2 a2  = __floats2half2_rn(1.058201e-3f, 1.058201e-3f);  // 1/945
    const __half2 a1  = __floats2half2_rn(0.1111111f, 0.1111111f);      // 1/9
    const __half2 d2  = __floats2half2_rn(0.0158730f, 0.0158730f);      // 1/63
    const __half2 d1  = __floats2half2_rn(0.4444444f, 0.4444444f);      // 4/9
    const __half2 s3  = __floats2half2_rn(-1.24884e-3f, -1.24884e-3f);
    const __half2 s2  = __floats2half2_rn(3.148607e-2f, 3.148607e-2f);
    const __half2 s1  = __floats2half2_rn(-0.2682411f, -0.2682411f);
    const __half2 s0  = __floats2half2_rn(0.9589143f, 0.9589143f);

    __half2 xc = __hmin2(__hmax2(x, ncl), cl);
    __half2 u  = __hmul2(xc, xc);
    __half2 np = __hfma2(a2, u, a1);
    np = __hfma2(np, u, one);
    __half2 N = __hmul2(xc, np);
    __half2 D = __hfma2(d2, u, d1);
    D = __hfma2(D, u, one);
    __half2 nD = __hneg2(D);
    __half2 y = __hfma2(s3, u, s2);
    y = __hfma2(y, u, s1);
    y = __hfma2(y, u, s0);
#pragma unroll
    for (int i = 0; i < 3; ++i) {
        __half2 e = __hfma2(nD, y, two);
        y = __hmul2(y, e);
    }
    return __hmul2(N, y);
}

// ---------------------------------------------------------------------------
// Projection GEMM (unchanged from R3 best): C[r][h] = sum_e A[r][e] * W[h][e]
// 64x64 tile, 256 threads, 4x4 register tile, e-chunk 32.
// ---------------------------------------------------------------------------
__global__ __launch_bounds__(256) void proj_kernel(
    const float* __restrict__ Aq, const float* __restrict__ Wq,
    const float* __restrict__ Ak, const float* __restrict__ Wk)
{
    const float* A; const float* W; float* C;
    if (blockIdx.z == 0) { A = Aq; W = Wq; C = (float*)g_qv; }
    else                 { A = Ak; W = Wk; C = (float*)g_kv; }

    const int row0 = blockIdx.x * 64;
    const int col0 = blockIdx.y * 64;

    __shared__ __align__(16) float As[32][68];
    __shared__ __align__(16) float Ws[32][68];

    const int tid = threadIdx.x;
    const int tx = tid & 15;
    const int ty = tid >> 4;

    float c[4][4];
#pragma unroll
    for (int i = 0; i < 4; ++i)
#pragma unroll
        for (int j = 0; j < 4; ++j) c[i][j] = 0.0f;

    for (int e0 = 0; e0 < EE; e0 += 32) {
        __syncthreads();
#pragma unroll
        for (int i = 0; i < 2; ++i) {
            const int idx = tid + i * 256;
            const int r  = idx >> 3;
            const int e8 = idx & 7;
            float4 va = *(const float4*)(A + (size_t)(row0 + r) * EE + e0 + 4 * e8);
            As[4 * e8 + 0][r] = va.x;
            As[4 * e8 + 1][r] = va.y;
            As[4 * e8 + 2][r] = va.z;
            As[4 * e8 + 3][r] = va.w;
            float4 vw = *(const float4*)(W + (size_t)(col0 + r) * EE + e0 + 4 * e8);
            Ws[4 * e8 + 0][r] = vw.x;
            Ws[4 * e8 + 1][r] = vw.y;
            Ws[4 * e8 + 2][r] = vw.z;
            Ws[4 * e8 + 3][r] = vw.w;
        }
        __syncthreads();
#pragma unroll
        for (int e = 0; e < 32; ++e) {
            float4 a4 = *(const float4*)(&As[e][4 * ty]);
            float4 w4 = *(const float4*)(&Ws[e][4 * tx]);
            float av[4] = {a4.x, a4.y, a4.z, a4.w};
            float wv[4] = {w4.x, w4.y, w4.z, w4.w};
#pragma unroll
            for (int i = 0; i < 4; ++i)
#pragma unroll
                for (int j = 0; j < 4; ++j)
                    c[i][j] = fmaf(av[i], wv[j], c[i][j]);
        }
    }

#pragma unroll
    for (int i = 0; i < 4; ++i) {
        float4 o = make_float4(c[i][0], c[i][1], c[i][2], c[i][3]);
        *(float4*)(C + (size_t)(row0 + 4 * ty + i) * HH + col0 + 4 * tx) = o;
    }
}

// ---------------------------------------------------------------------------
// Scores kernel, DUAL-PIPE tanh:
//   h elements m=0,1 (first 128 h)  -> MUFU tanh.approx.f16x2
//   h elements m=2,3 (second 128 h) -> FMA-pipe Pade tanh (tanh_pade2)
// Everything else identical to R3 (measured-best structure).
// ---------------------------------------------------------------------------
__global__ __launch_bounds__(256) void scores_kernel(const float* __restrict__ w_v)
{
    __shared__ __align__(16) __half2 kt[32 * 128];   // 16 KB

    const int tid  = threadIdx.x;
    const int w    = tid >> 5;
    const int lane = tid & 31;
    const int kl   = lane >> 3;
    const int hg   = lane & 7;

    const int bx = blockIdx.x;
    const int b  = bx >> 8;
    const int qt = (bx >> 2) & 63;
    const int ks = bx & 3;
    const int qi = qt * 8 + w;

    const float* gq = (const float*)g_qv;
    const float* gk = (const float*)g_kv;
    float*       gs = (float*)g_sv;

    const float4* qrow = (const float4*)(gq + (size_t)(b * QQ + qi) * HH);
    const float4* wv4  = (const float4*)w_v;
    __half2 qp[4][4], wp[4][4];
#pragma unroll
    for (int m = 0; m < 4; ++m) {
        float4 qa = qrow[2 * hg + 16 * m];
        float4 qb = qrow[2 * hg + 16 * m + 1];
        qp[m][0] = __floats2half2_rn(qa.x, qa.y);
        qp[m][1] = __floats2half2_rn(qa.z, qa.w);
        qp[m][2] = __floats2half2_rn(qb.x, qb.y);
        qp[m][3] = __floats2half2_rn(qb.z, qb.w);
        float4 wa = wv4[2 * hg + 16 * m];
        float4 wb = wv4[2 * hg + 16 * m + 1];
        wp[m][0] = __floats2half2_rn(wa.x, wa.y);
        wp[m][1] = __floats2half2_rn(wa.z, wa.w);
        wp[m][2] = __floats2half2_rn(wb.x, wb.y);
        wp[m][3] = __floats2half2_rn(wb.z, wb.w);
    }

    for (int t = 0; t < 4; ++t) {
        const int kbase = ks * 128 + t * 32;
        __syncthreads();
        {
            const float4* ksrc = (const float4*)(gk + (size_t)(b * KK + kbase) * HH);
#pragma unroll
            for (int j = 0; j < 8; ++j) {
                const int idx = tid + j * 256;
                const int key = idx >> 6;
                const int i4  = idx & 63;
                float4 v = ksrc[idx];
                __half2* dst = kt + key * 128 + 2 * i4;
                dst[0] = __floats2half2_rn(v.x, v.y);
                dst[1] = __floats2half2_rn(v.z, v.w);
            }
        }
        __syncthreads();

        float* srow = gs + (size_t)(b * QQ + qi) * KK + kbase;

#pragma unroll 2
        for (int g = 0; g < 8; ++g) {
            const int key = g * 4 + kl;
            const uint4* krow = (const uint4*)(kt + key * 128);

            __half2 acc0 = __floats2half2_rn(0.f, 0.f);
            __half2 acc1 = acc0, acc2 = acc0, acc3 = acc0;

            // m = 0,1 : MUFU tanh path
#pragma unroll
            for (int m = 0; m < 2; ++m) {
                uint4 kv = krow[hg + 8 * m];
                __half2 k0 = *(__half2*)&kv.x;
                __half2 k1 = *(__half2*)&kv.y;
                __half2 k2 = *(__half2*)&kv.z;
                __half2 k3 = *(__half2*)&kv.w;
                acc0 = __hfma2(wp[m][0], tanh2(__hadd2(qp[m][0], k0)), acc0);
                acc1 = __hfma2(wp[m][1], tanh2(__hadd2(qp[m][1], k1)), acc1);
                acc2 = __hfma2(wp[m][2], tanh2(__hadd2(qp[m][2], k2)), acc2);
                acc3 = __hfma2(wp[m][3], tanh2(__hadd2(qp[m][3], k3)), acc3);
            }
            // m = 2,3 : FMA-pipe Pade tanh path (runs under the MUFU shadow)
#pragma unroll
            for (int m = 2; m < 4; ++m) {
                uint4 kv = krow[hg + 8 * m];
                __half2 k0 = *(__half2*)&kv.x;
                __half2 k1 = *(__half2*)&kv.y;
                __half2 k2 = *(__half2*)&kv.z;
                __half2 k3 = *(__half2*)&kv.w;
                acc0 = __hfma2(wp[m][0], tanh_pade2(__hadd2(qp[m][0], k0)), acc0);
                acc1 = __hfma2(wp[m][1], tanh_pade2(__hadd2(qp[m][1], k1)), acc1);
                acc2 = __hfma2(wp[m][2], tanh_pade2(__hadd2(qp[m][2], k2)), acc2);
                acc3 = __hfma2(wp[m][3], tanh_pade2(__hadd2(qp[m][3], k3)), acc3);
            }

            float2 f0 = __half22float2(acc0);
            float2 f1 = __half22float2(acc1);
            float2 f2 = __half22float2(acc2);
            float2 f3 = __half22float2(acc3);
            float s = ((f0.x + f0.y) + (f1.x + f1.y)) +
                      ((f2.x + f2.y) + (f3.x + f3.y));

            s += __shfl_xor_sync(0xffffffffu, s, 1);
            s += __shfl_xor_sync(0xffffffffu, s, 2);
            s += __shfl_xor_sync(0xffffffffu, s, 4);
            float v = __shfl_sync(0xffffffffu, s, (lane & 3) * 8);
            if (lane < 4) srow[g * 4 + lane] = v;
        }
    }
}

// ---------------------------------------------------------------------------
// Softmax over K + attn @ V (unchanged from R3).
// ---------------------------------------------------------------------------
__global__ __launch_bounds__(512) void softmax_av_kernel(
    const float* __restrict__ values, float* __restrict__ out)
{
    __shared__ __align__(16) float p[16 * 512];
    __shared__ float invs[16];

    const int bx = blockIdx.x;
    const int b  = bx >> 5;
    const int qt = bx & 31;
    const int tid = threadIdx.x;

    {
        const float4* src = (const float4*)((const float*)g_sv + (size_t)(b * QQ + qt * 16) * KK);
        float4* dst = (float4*)p;
#pragma unroll
        for (int j = 0; j < 4; ++j)
            dst[tid + j * 512] = src[tid + j * 512];
    }
    __syncthreads();

    {
        const int w = tid >> 5, lane = tid & 31;
        float* row = p + w * 512;
        float m = -1e30f;
#pragma unroll
        for (int j = 0; j < 16; ++j) m = fmaxf(m, row[lane + 32 * j]);
#pragma unroll
        for (int o = 16; o > 0; o >>= 1)
            m = fmaxf(m, __shfl_xor_sync(0xffffffffu, m, o));
        float sum = 0.0f;
#pragma unroll
        for (int j = 0; j < 16; ++j) {
            float e = __expf(row[lane + 32 * j] - m);
            row[lane + 32 * j] = e;
            sum += e;
        }
#pragma unroll
        for (int o = 16; o > 0; o >>= 1)
            sum += __shfl_xor_sync(0xffffffffu, sum, o);
        if (lane == 0) invs[w] = 1.0f / sum;
    }
    __syncthreads();

    const int dq = tid & 63;
    const int qp = tid >> 6;
    const float* p0r = p + (2 * qp) * 512;
    const float* p1r = p + (2 * qp + 1) * 512;
    const float4* V = (const float4*)(values + (size_t)b * KK * DVV);

    float4 acc0 = make_float4(0.f, 0.f, 0.f, 0.f);
    float4 acc1 = make_float4(0.f, 0.f, 0.f, 0.f);

#pragma unroll 4
    for (int k = 0; k < KK; ++k) {
        const float4 v = V[k * (DVV / 4) + dq];
        const float a = p0r[k];
        const float c = p1r[k];
        acc0.x = fmaf(a, v.x, acc0.x);
        acc0.y = fmaf(a, v.y, acc0.y);
        acc0.z = fmaf(a, v.z, acc0.z);
        acc0.w = fmaf(a, v.w, acc0.w);
        acc1.x = fmaf(c, v.x, acc1.x);
        acc1.y = fmaf(c, v.y, acc1.y);
        acc1.z = fmaf(c, v.z, acc1.z);
        acc1.w = fmaf(c, v.w, acc1.w);
    }

    const float i0 = invs[2 * qp];
    const float i1 = invs[2 * qp + 1];
    acc0.x *= i0; acc0.y *= i0; acc0.z *= i0; acc0.w *= i0;
    acc1.x *= i1; acc1.y *= i1; acc1.z *= i1; acc1.w *= i1;

    const int q0 = qt * 16 + 2 * qp;
    *(float4*)(out + (size_t)(b * QQ + q0) * DVV + 4 * dq)       = acc0;
    *(float4*)(out + (size_t)(b * QQ + q0 + 1) * DVV + 4 * dq)   = acc1;
}

// ---------------------------------------------------------------------------
extern "C" void kernel_launch(void* const* d_in, const int* in_sizes, int n_in,
                              void* d_out, int out_size)
{
    const float* queries = (const float*)d_in[0];
    const float* keys    = (const float*)d_in[1];
    const float* values  = (const float*)d_in[2];
    const float* W_q     = (const float*)d_in[3];
    const float* W_k     = (const float*)d_in[4];
    const float* w_v     = (const float*)d_in[5];
    float* out = (float*)d_out;

    proj_kernel<<<dim3(32, 4, 2), 256>>>(queries, W_q, keys, W_k);
    scores_kernel<<<1024, 256>>>(w_v);
    softmax_av_kernel<<<128, 512>>>(values, out);
}